// round 16
// baseline (speedup 1.0000x reference)
#include <cuda_runtime.h>
#include <cuda_bf16.h>
#include <math.h>
#include <stdint.h>

#define DMODEL 1024
#define NHEADS 16
#define DKH    64
#define DFF    4096
#define BATCH  2
#define SEQ    2048
#define MTOK   (BATCH*SEQ)
#define LDQKV  3072

#if defined(__CUDA_ARCH__) && (defined(__CUDA_ARCH_FEAT_SM103_ALL) || defined(__CUDA_ARCH_FEAT_SM100_ALL))
#define HAS_TCGEN05 1
#else
#define HAS_TCGEN05 0
#endif

// ---------------------------------------------------------------- scratch
static const long long SZ_TBF  = 8388608LL;
static const long long SZ_QKV  = 25165824LL;
static const long long SZ_TF   = 16777216LL;
static const long long SZ_HBF  = 33554432LL;
static const long long SZ_WQKV = 6291456LL;
static const long long SZ_WBF  = 2097152LL;
static const long long SZ_WFBF = 8388608LL;

static const long long O_XH    = 0;
static const long long O_XL    = O_XH   + SZ_TBF;
static const long long O_QKVH  = O_XL   + SZ_TBF;
static const long long O_QKVL  = O_QKVH + SZ_QKV;
static const long long O_VTH   = O_QKVL + SZ_QKV;
static const long long O_VTL   = O_VTH  + SZ_TBF;
static const long long O_CH    = O_VTL  + SZ_TBF;
static const long long O_CL    = O_CH   + SZ_TBF;
static const long long O_X1H   = O_CL   + SZ_TBF;
static const long long O_X1L   = O_X1H  + SZ_TBF;
static const long long O_AO    = O_X1L  + SZ_TBF;
static const long long O_X1    = O_AO   + SZ_TF;
static const long long O_FF    = O_X1   + SZ_TF;
static const long long O_HH    = O_FF   + SZ_TF;
static const long long O_HL    = O_HH   + SZ_HBF;
static const long long O_WQKVH = O_HL   + SZ_HBF;
static const long long O_WQKVL = O_WQKVH + SZ_WQKV;
static const long long O_WOH   = O_WQKVL + SZ_WQKV;
static const long long O_WOL   = O_WOH  + SZ_WBF;
static const long long O_W1H   = O_WOL  + SZ_WBF;
static const long long O_W1L   = O_W1H  + SZ_WFBF;
static const long long O_W2H   = O_W1L  + SZ_WFBF;
static const long long O_W2L   = O_W2H  + SZ_WFBF;
static const long long TOTAL_BYTES = O_W2L + SZ_WFBF;

__device__ __align__(1024) unsigned char g_buf[TOTAL_BYTES];

// ---------------------------------------------------------------- helpers
__device__ __forceinline__ uint32_t smem_u32(const void* p) {
    uint32_t a;
    asm("{ .reg .u64 t; cvta.to.shared.u64 t, %1; cvt.u32.u64 %0, t; }"
        : "=r"(a) : "l"(p));
    return a;
}

__device__ __forceinline__ void mbar_wait(uint32_t addr, uint32_t parity) {
    asm volatile(
        "{\n\t.reg .pred P;\n\t"
        "W%=:\n\t"
        "mbarrier.try_wait.parity.acquire.cta.shared::cta.b64 P, [%0], %1;\n\t"
        "@!P bra W%=;\n\t}"
        :: "r"(addr), "r"(parity) : "memory");
}

static __device__ const unsigned long long DESC_BASE =
    (2ULL << 61) | (1ULL << 46) | (64ULL << 32) | (1ULL << 16);
static __device__ const unsigned long long DESC64_BASE =
    (4ULL << 61) | (1ULL << 46) | (32ULL << 32) | (1ULL << 16);

__device__ __forceinline__ unsigned long long dsc(uint32_t a) {
    return DESC_BASE | ((a >> 4) & 0x3FFF);
}
__device__ __forceinline__ unsigned long long dsc64(uint32_t a) {
    return DESC64_BASE | ((a >> 4) & 0x3FFF);
}

template<int BN> __device__ __forceinline__ uint32_t idesc_v() {
    return (1u << 4) | (1u << 7) | (1u << 10) | ((uint32_t)(BN / 8) << 17) | (8u << 24);
}

__device__ __forceinline__ float gelu_exact(float v) {
    return 0.5f * v * (1.0f + erff(v * 0.70710678118654752f));
}

__device__ __forceinline__ void split2(float v, __nv_bfloat16& h, __nv_bfloat16& l) {
    h = __float2bfloat16(v);
    l = __float2bfloat16(v - __bfloat162float(h));
}

#if HAS_TCGEN05
__device__ __forceinline__ void tc_mma(uint32_t d, unsigned long long ad,
                                       unsigned long long bd, uint32_t idesc, uint32_t en) {
    asm volatile(
        "{\n\t.reg .pred p;\n\tsetp.ne.u32 p, %4, 0;\n\t"
        "tcgen05.mma.cta_group::1.kind::f16 [%0], %1, %2, %3, {%5,%5,%5,%5}, p;\n\t}"
        :: "r"(d), "l"(ad), "l"(bd), "r"(idesc), "r"(en), "r"(0u) : "memory");
}
__device__ __forceinline__ void tc_commit(uint32_t mbar) {
    asm volatile(
        "tcgen05.commit.cta_group::1.mbarrier::arrive::one.shared::cluster.b64 [%0];"
        :: "r"(mbar) : "memory");
}
#define LDTM_X32(r, a)                                                         \
    asm volatile(                                                              \
        "tcgen05.ld.sync.aligned.32x32b.x32.b32 "                              \
        "{%0,%1,%2,%3,%4,%5,%6,%7,%8,%9,%10,%11,%12,%13,%14,%15,"              \
        "%16,%17,%18,%19,%20,%21,%22,%23,%24,%25,%26,%27,%28,%29,%30,%31}, [%32];" \
        : "=r"((r)[0]),  "=r"((r)[1]),  "=r"((r)[2]),  "=r"((r)[3]),           \
          "=r"((r)[4]),  "=r"((r)[5]),  "=r"((r)[6]),  "=r"((r)[7]),           \
          "=r"((r)[8]),  "=r"((r)[9]),  "=r"((r)[10]), "=r"((r)[11]),          \
          "=r"((r)[12]), "=r"((r)[13]), "=r"((r)[14]), "=r"((r)[15]),          \
          "=r"((r)[16]), "=r"((r)[17]), "=r"((r)[18]), "=r"((r)[19]),          \
          "=r"((r)[20]), "=r"((r)[21]), "=r"((r)[22]), "=r"((r)[23]),          \
          "=r"((r)[24]), "=r"((r)[25]), "=r"((r)[26]), "=r"((r)[27]),          \
          "=r"((r)[28]), "=r"((r)[29]), "=r"((r)[30]), "=r"((r)[31])           \
        : "r"(a))
#define STTM_X32(a, r)                                                         \
    asm volatile(                                                              \
        "tcgen05.st.sync.aligned.32x32b.x32.b32 [%0], "                        \
        "{%1,%2,%3,%4,%5,%6,%7,%8,%9,%10,%11,%12,%13,%14,%15,%16,"             \
        "%17,%18,%19,%20,%21,%22,%23,%24,%25,%26,%27,%28,%29,%30,%31,%32};"    \
        :: "r"(a),                                                             \
           "r"((r)[0]),  "r"((r)[1]),  "r"((r)[2]),  "r"((r)[3]),              \
           "r"((r)[4]),  "r"((r)[5]),  "r"((r)[6]),  "r"((r)[7]),              \
           "r"((r)[8]),  "r"((r)[9]),  "r"((r)[10]), "r"((r)[11]),             \
           "r"((r)[12]), "r"((r)[13]), "r"((r)[14]), "r"((r)[15]),             \
           "r"((r)[16]), "r"((r)[17]), "r"((r)[18]), "r"((r)[19]),             \
           "r"((r)[20]), "r"((r)[21]), "r"((r)[22]), "r"((r)[23]),             \
           "r"((r)[24]), "r"((r)[25]), "r"((r)[26]), "r"((r)[27]),             \
           "r"((r)[28]), "r"((r)[29]), "r"((r)[30]), "r"((r)[31])              \
        : "memory")
#endif

// SW128 tile loader (128B rows) — flash
template<int ROWS>
__device__ __forceinline__ void cp_tile(uint32_t dst, const __nv_bfloat16* __restrict__ src,
                                        int ldsrc, int tid)
{
#pragma unroll
    for (int i = 0; i < ROWS / 32; ++i) {
        int idx = tid + i * 256;
        int r = idx >> 3, kb = (idx & 7) * 16;
        uint32_t off = (uint32_t)(r * 128 + kb);
        off ^= (off >> 3) & 0x70;
        asm volatile("cp.async.cg.shared.global [%0], [%1], 16;"
                     :: "r"(dst + off), "l"((const char*)(src + (long long)r * ldsrc) + kb));
    }
}

// SW64 tile loader (64B rows) — GEMM, K-chunk 32
template<int ROWS>
__device__ __forceinline__ void cp_tile64(uint32_t dst, const __nv_bfloat16* __restrict__ src,
                                          int ldsrc, int tid)
{
#pragma unroll
    for (int i = 0; i < ROWS / 64; ++i) {
        int idx = tid + i * 256;
        int r = idx >> 2, kb = (idx & 3) * 16;
        uint32_t off = (uint32_t)(r * 64 + kb);
        off ^= (off >> 3) & 0x30;
        asm volatile("cp.async.cg.shared.global [%0], [%1], 16;"
                     :: "r"(dst + off), "l"((const char*)(src + (long long)r * ldsrc) + kb));
    }
}

// ---------------------------------------------------------------- tcgen05 GEMM (R14 exact: 4-stage, 1 CTA/SM)
template<int BN, int EPI, int OUT>
__global__ __launch_bounds__(256)
void mma_gemm(const __nv_bfloat16* __restrict__ Ah, const __nv_bfloat16* __restrict__ Al,
              const __nv_bfloat16* __restrict__ Bh, const __nv_bfloat16* __restrict__ Bl,
              const float* __restrict__ bias,
              float* __restrict__ C, __nv_bfloat16* __restrict__ Ch, __nv_bfloat16* __restrict__ Cl,
              int K, int lda, int ldb, int ldc, float alpha)
{
#if HAS_TCGEN05
    constexpr uint32_t T_AL = 8192;
    constexpr uint32_t T_BH = 16384;
    constexpr uint32_t T_BL = 16384 + BN * 64;
    constexpr uint32_t SS   = (256 + 2 * BN) * 64;   // 48KB

    extern __shared__ unsigned char smraw[];
    const uint32_t smb  = smem_u32(smraw);
    const uint32_t MBAR = smb + 8;
    const uint32_t ST0  = smb + 1024;

    const int tid = threadIdx.x, wid = tid >> 5, lane = tid & 31;
    const int m0 = blockIdx.y * 128;
    const int n0 = blockIdx.x * BN;

    if (wid == 0) {
        asm volatile("tcgen05.alloc.cta_group::1.sync.aligned.shared::cta.b32 [%0], %1;"
                     :: "r"(smb), "r"((uint32_t)BN) : "memory");
        asm volatile("tcgen05.relinquish_alloc_permit.cta_group::1.sync.aligned;");
    }
    if (tid == 0)
        asm volatile("mbarrier.init.shared.b64 [%0], 1;" :: "r"(MBAR) : "memory");
    __syncthreads();
    uint32_t tmem;
    asm volatile("ld.shared.b32 %0, [%1];" : "=r"(tmem) : "r"(smb));

    const __nv_bfloat16* Ap  = Ah + (long long)m0 * lda;
    const __nv_bfloat16* Alp = Al + (long long)m0 * lda;
    const __nv_bfloat16* Bp  = Bh + (long long)n0 * ldb;
    const __nv_bfloat16* Blp = Bl + (long long)n0 * ldb;

    const int nch = K >> 5;

    // prologue: chunks 0..2 into stages 0..2
#pragma unroll
    for (int t = 0; t < 3; ++t) {
        const uint32_t st = ST0 + t * SS;
        const int k0 = t << 5;
        cp_tile64<128>(st,        Ap  + k0, lda, tid);
        cp_tile64<128>(st + T_AL, Alp + k0, lda, tid);
        cp_tile64<BN >(st + T_BH, Bp  + k0, ldb, tid);
        cp_tile64<BN >(st + T_BL, Blp + k0, ldb, tid);
        asm volatile("cp.async.commit_group;" ::: "memory");
    }

    for (int c = 0; c < nch; ++c) {
        const int rem = nch - 1 - c;
        if (rem >= 2)      asm volatile("cp.async.wait_group 2;" ::: "memory");
        else if (rem == 1) asm volatile("cp.async.wait_group 1;" ::: "memory");
        else               asm volatile("cp.async.wait_group 0;" ::: "memory");
        __syncthreads();
        asm volatile("fence.proxy.async.shared::cta;" ::: "memory");
        if (tid == 0) {
            const uint32_t st = ST0 + (uint32_t)(c & 3) * SS;
            const uint32_t ao[3] = {st, st, st + T_AL};
            const uint32_t bo[3] = {st + T_BH, st + T_BL, st + T_BH};
#pragma unroll
            for (int p = 0; p < 3; ++p) {
                unsigned long long ad = dsc64(ao[p]);
                unsigned long long bd = dsc64(bo[p]);
#pragma unroll
                for (int s = 0; s < 2; ++s) {
                    uint32_t en = (c > 0 || p > 0 || s > 0) ? 1u : 0u;
                    tc_mma(tmem, ad + s * 2, bd + s * 2, idesc_v<BN>(), en);
                }
            }
        }
        if (c > 0) mbar_wait(MBAR, (uint32_t)((c - 1) & 1));
        if (tid == 0) tc_commit(MBAR);
        if (c + 3 < nch) {
            const uint32_t st = ST0 + (uint32_t)((c + 3) & 3) * SS;
            const int k0 = (c + 3) << 5;
            cp_tile64<128>(st,        Ap  + k0, lda, tid);
            cp_tile64<128>(st + T_AL, Alp + k0, lda, tid);
            cp_tile64<BN >(st + T_BH, Bp  + k0, ldb, tid);
            cp_tile64<BN >(st + T_BL, Blp + k0, ldb, tid);
            asm volatile("cp.async.commit_group;" ::: "memory");
        }
    }
    mbar_wait(MBAR, (uint32_t)((nch - 1) & 1));
    asm volatile("tcgen05.fence::after_thread_sync;" ::: "memory");

    const int half = wid >> 2;
    const int m = m0 + (wid & 3) * 32 + lane;
    const int colBase = half * (BN / 2);
#pragma unroll
    for (int c0 = 0; c0 < BN / 2; c0 += 32) {
        uint32_t r[32];
        LDTM_X32(r, tmem + colBase + c0);
        asm volatile("tcgen05.wait::ld.sync.aligned;" ::: "memory");

#pragma unroll
        for (int j = 0; j < 32; j += 4) {
            float v[4];
#pragma unroll
            for (int q = 0; q < 4; ++q) {
                float t = __uint_as_float(r[j + q]) * alpha;
                if (EPI >= 1) t += bias[n0 + colBase + c0 + j + q];
                if (EPI == 2) t = gelu_exact(t);
                v[q] = t;
            }
            const long long cix = (long long)m * ldc + n0 + colBase + c0 + j;
            if (OUT == 0) {
                float4 o; o.x = v[0]; o.y = v[1]; o.z = v[2]; o.w = v[3];
                *(float4*)(C + cix) = o;
            } else {
                __nv_bfloat16 h[4], l[4];
#pragma unroll
                for (int q = 0; q < 4; ++q) split2(v[q], h[q], l[q]);
                uint2 uh, ul;
                uh.x = ((uint32_t)__bfloat16_as_ushort(h[1]) << 16) | __bfloat16_as_ushort(h[0]);
                uh.y = ((uint32_t)__bfloat16_as_ushort(h[3]) << 16) | __bfloat16_as_ushort(h[2]);
                ul.x = ((uint32_t)__bfloat16_as_ushort(l[1]) << 16) | __bfloat16_as_ushort(l[0]);
                ul.y = ((uint32_t)__bfloat16_as_ushort(l[3]) << 16) | __bfloat16_as_ushort(l[2]);
                *(uint2*)(Ch + cix) = uh;
                *(uint2*)(Cl + cix) = ul;
            }
        }
    }

    __syncthreads();
    if (wid == 0)
        asm volatile("tcgen05.dealloc.cta_group::1.sync.aligned.b32 %0, %1;"
                     :: "r"(tmem), "r"((uint32_t)BN));
#else
    __trap();
#endif
}

// ---------------------------------------------------------------- flash attention (unchanged)
#if HAS_TCGEN05
__device__ __forceinline__ void issue_smma(uint32_t tmem, uint32_t qh, uint32_t ql, uint32_t st) {
    const uint32_t aT[3] = {qh, qh, ql};
    const uint32_t bT[3] = {st, st + 16384, st};
#pragma unroll
    for (int p = 0; p < 3; ++p) {
        unsigned long long ad = dsc(aT[p]);
        unsigned long long bd = dsc(bT[p]);
#pragma unroll
        for (int s = 0; s < 4; ++s)
            tc_mma(tmem + 64, ad + s * 2, bd + s * 2, idesc_v<128>(),
                   (p > 0 || s > 0) ? 1u : 0u);
    }
}

__device__ __forceinline__ void issue_pv(uint32_t tmem, uint32_t ph, uint32_t pl,
                                         uint32_t st, int first) {
    const uint32_t aT[3] = {ph, ph, pl};
    const uint32_t bT[3] = {st + 32768, st + 49152, st + 32768};
#pragma unroll
    for (int p = 0; p < 3; ++p)
#pragma unroll
        for (int c = 0; c < 2; ++c) {
            unsigned long long ad = dsc(aT[p] + c * 16384);
            unsigned long long bd = dsc(bT[p] + c * 8192);
#pragma unroll
            for (int s = 0; s < 4; ++s)
                tc_mma(tmem, ad + s * 2, bd + s * 2, idesc_v<64>(),
                       (first && p == 0 && c == 0 && s == 0) ? 0u : 1u);
        }
}
#endif

__global__ __launch_bounds__(256)
void flash_attn_k(const __nv_bfloat16* __restrict__ Qh, const __nv_bfloat16* __restrict__ Ql,
                  const __nv_bfloat16* __restrict__ Kh, const __nv_bfloat16* __restrict__ Kl,
                  const __nv_bfloat16* __restrict__ Vth, const __nv_bfloat16* __restrict__ Vtl,
                  const int* __restrict__ mask,
                  __nv_bfloat16* __restrict__ Ch, __nv_bfloat16* __restrict__ Cl, int ldq)
{
#if HAS_TCGEN05
    extern __shared__ unsigned char smraw[];
    const uint32_t smb  = smem_u32(smraw);
    const uint32_t SBAR = smb + 8;
    const uint32_t PBAR = smb + 16;
    float* biasS  = (float*)(smraw + 512);
    float* redMax = (float*)(smraw + 1024);
    float* redSum = (float*)(smraw + 2048);
    const uint32_t SM_QH = smb + 3072,  SM_QL = SM_QH + 16384;
    const uint32_t SM_PH = smb + 35840, SM_PL = SM_PH + 32768;
    const uint32_t ST0   = smb + 101376;
    constexpr uint32_t STS_ = 65536;

    const int tid = threadIdx.x, wid = tid >> 5, lane = tid & 31;
    const int sub = wid & 3;
    const int colh = wid >> 2;
    const int rowP = sub * 32 + lane;
    const int qt = blockIdx.x, bh = blockIdx.y, b = bh >> 4, h = bh & 15;

    const long long qoff  = ((long long)(b * SEQ + qt * 128)) * ldq + h * 64;
    const long long kbase = (long long)b * SEQ * ldq + h * 64;
    const long long vbase = (long long)bh * (64LL * SEQ);

    if (wid == 0) {
        asm volatile("tcgen05.alloc.cta_group::1.sync.aligned.shared::cta.b32 [%0], %1;"
                     :: "r"(smb), "r"(256u) : "memory");
        asm volatile("tcgen05.relinquish_alloc_permit.cta_group::1.sync.aligned;");
    }
    if (tid == 0) {
        asm volatile("mbarrier.init.shared.b64 [%0], 1;" :: "r"(SBAR) : "memory");
        asm volatile("mbarrier.init.shared.b64 [%0], 1;" :: "r"(PBAR) : "memory");
    }
    __syncthreads();
    uint32_t tmem;
    asm volatile("ld.shared.b32 %0, [%1];" : "=r"(tmem) : "r"(smb));

    cp_tile<128>(SM_QH, Qh + qoff, ldq, tid);
    cp_tile<128>(SM_QL, Ql + qoff, ldq, tid);
#pragma unroll
    for (int t = 0; t < 2; ++t) {
        const uint32_t st = ST0 + t * STS_;
        const long long ko = kbase + (long long)t * 128 * ldq;
        const long long vo = vbase + t * 128;
        cp_tile<128>(st,         Kh  + ko, ldq, tid);
        cp_tile<128>(st + 16384, Kl  + ko, ldq, tid);
        cp_tile<64>(st + 32768,  Vth + vo,      SEQ, tid);
        cp_tile<64>(st + 40960,  Vth + vo + 64, SEQ, tid);
        cp_tile<64>(st + 49152,  Vtl + vo,      SEQ, tid);
        cp_tile<64>(st + 57344,  Vtl + vo + 64, SEQ, tid);
        asm volatile("cp.async.commit_group;" ::: "memory");
    }
    asm volatile("cp.async.wait_group 1;" ::: "memory");
    __syncthreads();
    asm volatile("fence.proxy.async.shared::cta;" ::: "memory");
    if (tid == 0) {
        asm volatile("tcgen05.fence::after_thread_sync;" ::: "memory");
        issue_smma(tmem, SM_QH, SM_QL, ST0);
        tc_commit(SBAR);
    }

    float mold = -3.4e38f, lrun = 0.0f;
    int sPh = 0, pPh = 0;

    for (int i = 0; i < 16; ++i) {
        mbar_wait(SBAR, (uint32_t)(sPh & 1)); ++sPh;
        asm volatile("tcgen05.fence::after_thread_sync;" ::: "memory");

        if (i >= 1 && i < 15) {
            const uint32_t st = ST0 + (((i + 1) & 1) ? STS_ : 0u);
            const long long ko = kbase + (long long)(i + 1) * 128 * ldq;
            cp_tile<128>(st,         Kh + ko, ldq, tid);
            cp_tile<128>(st + 16384, Kl + ko, ldq, tid);
            asm volatile("cp.async.commit_group;" ::: "memory");
        }
        if (tid < 128)
            biasS[tid] = (mask[b * SEQ + i * 128 + tid] == 0) ? -1e9f : 0.0f;
        __syncthreads();

        float sv[64];
        {
            uint32_t r[32];
#pragma unroll
            for (int g = 0; g < 2; ++g) {
                LDTM_X32(r, tmem + 64 + colh * 64 + g * 32);
                asm volatile("tcgen05.wait::ld.sync.aligned;" ::: "memory");
#pragma unroll
                for (int j = 0; j < 32; ++j) sv[g * 32 + j] = __uint_as_float(r[j]);
            }
        }
        asm volatile("tcgen05.fence::before_thread_sync;" ::: "memory");

        if (i + 1 < 16) {
            asm volatile("cp.async.wait_group 0;" ::: "memory");
            __syncthreads();
            asm volatile("fence.proxy.async.shared::cta;" ::: "memory");
            if (tid == 0) {
                asm volatile("tcgen05.fence::after_thread_sync;" ::: "memory");
                issue_smma(tmem, SM_QH, SM_QL, ST0 + (((i + 1) & 1) ? STS_ : 0u));
                tc_commit(SBAR);
            }
        } else {
            asm volatile("cp.async.wait_group 0;" ::: "memory");
            __syncthreads();
        }

        float pmax = -3.4e38f;
#pragma unroll
        for (int j = 0; j < 64; ++j) {
            float s = sv[j] * 0.125f + biasS[colh * 64 + j];
            sv[j] = s;
            pmax = fmaxf(pmax, s);
        }
        redMax[colh * 128 + rowP] = pmax;
        __syncthreads();
        const float mnew = fmaxf(mold, fmaxf(redMax[rowP], redMax[128 + rowP]));
        const float alpha = __expf(mold - mnew);

        if (i > 0) {
            mbar_wait(PBAR, (uint32_t)(pPh & 1)); ++pPh;
            asm volatile("tcgen05.fence::after_thread_sync;" ::: "memory");
            if (__any_sync(0xffffffffu, mnew != mold)) {
                uint32_t r[32];
                LDTM_X32(r, tmem + colh * 32);
                asm volatile("tcgen05.wait::ld.sync.aligned;" ::: "memory");
#pragma unroll
                for (int j = 0; j < 32; ++j)
                    r[j] = __float_as_uint(__uint_as_float(r[j]) * alpha);
                STTM_X32(tmem + ((uint32_t)sub << 21) + colh * 32, r);
                asm volatile("tcgen05.wait::st.sync.aligned;" ::: "memory");
            }
            if (i < 15) {
                const uint32_t st = ST0 + (((i + 1) & 1) ? STS_ : 0u);
                const long long vo = vbase + (long long)(i + 1) * 128;
                cp_tile<64>(st + 32768, Vth + vo,      SEQ, tid);
                cp_tile<64>(st + 40960, Vth + vo + 64, SEQ, tid);
                cp_tile<64>(st + 49152, Vtl + vo,      SEQ, tid);
                cp_tile<64>(st + 57344, Vtl + vo + 64, SEQ, tid);
                asm volatile("cp.async.commit_group;" ::: "memory");
            }
        }
        mold = mnew;

        float ls = 0.0f;
#pragma unroll
        for (int j = 0; j < 64; ++j) {
            float p = __expf(sv[j] - mnew);
            sv[j] = p;
            ls += p;
        }
        redSum[colh * 128 + rowP] = ls;

        {
            const uint32_t baseH = SM_PH + colh * 16384;
            const uint32_t baseL = SM_PL + colh * 16384;
#pragma unroll
            for (int j0 = 0; j0 < 64; j0 += 8) {
                uint32_t hw[4], lw[4];
#pragma unroll
                for (int q = 0; q < 4; ++q) {
                    float v0 = sv[j0 + 2 * q], v1 = sv[j0 + 2 * q + 1];
                    __nv_bfloat16 h0, l0, h1, l1;
                    split2(v0, h0, l0); split2(v1, h1, l1);
                    hw[q] = ((uint32_t)__bfloat16_as_ushort(h1) << 16) | __bfloat16_as_ushort(h0);
                    lw[q] = ((uint32_t)__bfloat16_as_ushort(l1) << 16) | __bfloat16_as_ushort(l0);
                }
                uint32_t off = (uint32_t)(rowP * 128 + j0 * 2);
                off ^= (off >> 3) & 0x70;
                asm volatile("st.shared.v4.b32 [%0], {%1,%2,%3,%4};"
                             :: "r"(baseH + off), "r"(hw[0]), "r"(hw[1]), "r"(hw[2]), "r"(hw[3]));
                asm volatile("st.shared.v4.b32 [%0], {%1,%2,%3,%4};"
                             :: "r"(baseL + off), "r"(lw[0]), "r"(lw[1]), "r"(lw[2]), "r"(lw[3]));
            }
        }
        asm volatile("tcgen05.fence::before_thread_sync;" ::: "memory");
        asm volatile("fence.proxy.async.shared::cta;" ::: "memory");
        __syncthreads();
        lrun = lrun * alpha + redSum[rowP] + redSum[128 + rowP];
        if (tid == 0) {
            asm volatile("tcgen05.fence::after_thread_sync;" ::: "memory");
            issue_pv(tmem, SM_PH, SM_PL, ST0 + ((i & 1) ? STS_ : 0u), i == 0);
            tc_commit(PBAR);
        }
    }

    mbar_wait(PBAR, (uint32_t)(pPh & 1)); ++pPh;
    asm volatile("tcgen05.fence::after_thread_sync;" ::: "memory");

    {
        uint32_t r[32];
        LDTM_X32(r, tmem + colh * 32);
        asm volatile("tcgen05.wait::ld.sync.aligned;" ::: "memory");
        asm volatile("tcgen05.fence::before_thread_sync;" ::: "memory");
        const float inv = 1.0f / lrun;
        const long long row = (long long)b * SEQ + qt * 128 + rowP;
        const long long cix = row * DMODEL + h * 64 + colh * 32;
#pragma unroll
        for (int j = 0; j < 32; j += 4) {
            __nv_bfloat16 hh[4], ll[4];
#pragma unroll
            for (int q = 0; q < 4; ++q) {
                float v = __uint_as_float(r[j + q]) * inv;
                split2(v, hh[q], ll[q]);
            }
            uint2 uh, ul;
            uh.x = ((uint32_t)__bfloat16_as_ushort(hh[1]) << 16) | __bfloat16_as_ushort(hh[0]);
            uh.y = ((uint32_t)__bfloat16_as_ushort(hh[3]) << 16) | __bfloat16_as_ushort(hh[2]);
            ul.x = ((uint32_t)__bfloat16_as_ushort(ll[1]) << 16) | __bfloat16_as_ushort(ll[0]);
            ul.y = ((uint32_t)__bfloat16_as_ushort(ll[3]) << 16) | __bfloat16_as_ushort(ll[2]);
            *(uint2*)(Ch + cix + j) = uh;
            *(uint2*)(Cl + cix + j) = ul;
        }
    }
    __syncthreads();
    if (wid == 0)
        asm volatile("tcgen05.dealloc.cta_group::1.sync.aligned.b32 %0, %1;"
                     :: "r"(tmem), "r"(256u));
#else
    __trap();
#endif
}

// ---------------------------------------------------------------- prep kernels
__global__ __launch_bounds__(256)
void split_k(const float4* __restrict__ in, __nv_bfloat16* __restrict__ oh,
             __nv_bfloat16* __restrict__ ol, int n4)
{
    int i = blockIdx.x * 256 + threadIdx.x;
    if (i >= n4) return;
    float4 v = in[i];
    __nv_bfloat16 h[4], l[4];
    split2(v.x, h[0], l[0]); split2(v.y, h[1], l[1]);
    split2(v.z, h[2], l[2]); split2(v.w, h[3], l[3]);
    uint2 uh, ul;
    uh.x = ((uint32_t)__bfloat16_as_ushort(h[1]) << 16) | __bfloat16_as_ushort(h[0]);
    uh.y = ((uint32_t)__bfloat16_as_ushort(h[3]) << 16) | __bfloat16_as_ushort(h[2]);
    ul.x = ((uint32_t)__bfloat16_as_ushort(l[1]) << 16) | __bfloat16_as_ushort(l[0]);
    ul.y = ((uint32_t)__bfloat16_as_ushort(l[3]) << 16) | __bfloat16_as_ushort(l[2]);
    ((uint2*)oh)[i] = uh;
    ((uint2*)ol)[i] = ul;
}

__global__ __launch_bounds__(256)
void transpose_split_k(const float* __restrict__ in, __nv_bfloat16* __restrict__ oh,
                       __nv_bfloat16* __restrict__ ol, int ldin, int ldout)
{
    __shared__ float t[32][33];
    const int c0 = blockIdx.x * 32, r0 = blockIdx.y * 32;
    const int tx = threadIdx.x & 31, ty = threadIdx.x >> 5;
#pragma unroll
    for (int i = 0; i < 32; i += 8)
        t[ty + i][tx] = in[(long long)(r0 + ty + i) * ldin + c0 + tx];
    __syncthreads();
#pragma unroll
    for (int i = 0; i < 32; i += 8) {
        float v = t[tx][ty + i];
        __nv_bfloat16 h, l; split2(v, h, l);
        long long o = (long long)(c0 + ty + i) * ldout + r0 + tx;
        oh[o] = h; ol[o] = l;
    }
}

__global__ __launch_bounds__(256)
void w4_transpose_k(const float* __restrict__ wq, const float* __restrict__ wk,
                    const float* __restrict__ wv, const float* __restrict__ wo,
                    __nv_bfloat16* __restrict__ qkvh, __nv_bfloat16* __restrict__ qkvl,
                    __nv_bfloat16* __restrict__ woh, __nv_bfloat16* __restrict__ wol)
{
    __shared__ float t[32][33];
    const int z = blockIdx.z;
    const float* in = (z == 0) ? wq : (z == 1) ? wk : (z == 2) ? wv : wo;
    __nv_bfloat16* oh = (z < 3) ? qkvh + (long long)z * 1048576 : woh;
    __nv_bfloat16* ol = (z < 3) ? qkvl + (long long)z * 1048576 : wol;
    const int c0 = blockIdx.x * 32, r0 = blockIdx.y * 32;
    const int tx = threadIdx.x & 31, ty = threadIdx.x >> 5;
#pragma unroll
    for (int i = 0; i < 32; i += 8)
        t[ty + i][tx] = in[(long long)(r0 + ty + i) * 1024 + c0 + tx];
    __syncthreads();
#pragma unroll
    for (int i = 0; i < 32; i += 8) {
        float v = t[tx][ty + i];
        __nv_bfloat16 h, l; split2(v, h, l);
        long long o = (long long)(c0 + ty + i) * 1024 + r0 + tx;
        oh[o] = h; ol[o] = l;
    }
}

__global__ __launch_bounds__(256)
void transpose_bf16_k(const __nv_bfloat16* __restrict__ ih, const __nv_bfloat16* __restrict__ il,
                      __nv_bfloat16* __restrict__ oh, __nv_bfloat16* __restrict__ ol,
                      int ldin, int ldout,
                      long long iB, long long iH, long long oB, long long oH, int nH)
{
    __shared__ unsigned short th[32][33], tl[32][33];
    const int z = blockIdx.z, zb = z / nH, zh = z - zb * nH;
    ih += (long long)zb * iB + (long long)zh * iH;
    il += (long long)zb * iB + (long long)zh * iH;
    const long long oo = (long long)zb * oB + (long long)zh * oH;
    const int c0 = blockIdx.x * 32, r0 = blockIdx.y * 32;
    const int tx = threadIdx.x & 31, ty = threadIdx.x >> 5;
#pragma unroll
    for (int i = 0; i < 32; i += 8) {
        long long ix = (long long)(r0 + ty + i) * ldin + c0 + tx;
        th[ty + i][tx] = __bfloat16_as_ushort(ih[ix]);
        tl[ty + i][tx] = __bfloat16_as_ushort(il[ix]);
    }
    __syncthreads();
#pragma unroll
    for (int i = 0; i < 32; i += 8) {
        long long o = oo + (long long)(c0 + ty + i) * ldout + r0 + tx;
        oh[o] = __ushort_as_bfloat16(th[tx][ty + i]);
        ol[o] = __ushort_as_bfloat16(tl[tx][ty + i]);
    }
}

template<bool SPLIT>
__global__ __launch_bounds__(256)
void add_ln_k(const float* __restrict__ a, const float* __restrict__ rres,
              const float* __restrict__ g, const float* __restrict__ be,
              float* __restrict__ out, __nv_bfloat16* __restrict__ oh,
              __nv_bfloat16* __restrict__ ol)
{
    const long long row = blockIdx.x;
    const float* pa = a + row * DMODEL;
    const float* pr = rres + row * DMODEL;
    const int t = threadIdx.x;
    constexpr int PER = DMODEL / 256;

    float v[PER];
    float s = 0.0f, s2 = 0.0f;
#pragma unroll
    for (int i = 0; i < PER; i++) {
        int c = t + i * 256;
        float x = pa[c] + pr[c];
        v[i] = x; s += x; s2 += x * x;
    }
    __shared__ float r1[256], r2[256];
    r1[t] = s; r2[t] = s2; __syncthreads();
    for (int st = 128; st > 0; st >>= 1) {
        if (t < st) { r1[t] += r1[t + st]; r2[t] += r2[t + st]; }
        __syncthreads();
    }
    const float mu  = r1[0] * (1.0f / DMODEL);
    const float var = r2[0] * (1.0f / DMODEL) - mu * mu;
    const float inv = rsqrtf(var + 1e-6f);
#pragma unroll
    for (int i = 0; i < PER; i++) {
        int c = t + i * 256;
        float y = (v[i] - mu) * inv * g[c] + be[c];
        out[row * DMODEL + c] = y;
        if (SPLIT) {
            __nv_bfloat16 h, l; split2(y, h, l);
            oh[row * DMODEL + c] = h;
            ol[row * DMODEL + c] = l;
        }
    }
}

// ---------------------------------------------------------------- launch
extern "C" void kernel_launch(void* const* d_in, const int* in_sizes, int n_in,
                              void* d_out, int out_size)
{
    const float* x    = (const float*)d_in[0];
    const int*   mask = (const int*)  d_in[1];
    const float* wq   = (const float*)d_in[2];
    const float* wk   = (const float*)d_in[3];
    const float* wv   = (const float*)d_in[4];
    const float* wo   = (const float*)d_in[5];
    const float* wo_b = (const float*)d_in[6];
    const float* w1   = (const float*)d_in[7];
    const float* b1   = (const float*)d_in[8];
    const float* w2   = (const float*)d_in[9];
    const float* b2   = (const float*)d_in[10];
    const float* g1   = (const float*)d_in[11];
    const float* be1  = (const float*)d_in[12];
    const float* g2   = (const float*)d_in[13];
    const float* be2  = (const float*)d_in[14];
    float* out = (float*)d_out;

    unsigned char* gb = nullptr;
    cudaGetSymbolAddress((void**)&gb, g_buf);
#define BP(T, off) ((T*)(gb + (off)))
    __nv_bfloat16 *Xh = BP(__nv_bfloat16, O_XH),   *Xl = BP(__nv_bfloat16, O_XL);
    __nv_bfloat16 *QKVh = BP(__nv_bfloat16, O_QKVH), *QKVl = BP(__nv_bfloat16, O_QKVL);
    __nv_bfloat16 *Vth = BP(__nv_bfloat16, O_VTH), *Vtl = BP(__nv_bfloat16, O_VTL);
    __nv_bfloat16 *Cxh = BP(__nv_bfloat16, O_CH),  *Cxl = BP(__nv_bfloat16, O_CL);
    __nv_bfloat16 *X1h = BP(__nv_bfloat16, O_X1H), *X1l = BP(__nv_bfloat16, O_X1L);
    float *AO = BP(float, O_AO), *X1 = BP(float, O_X1), *FF = BP(float, O_FF);
    __nv_bfloat16 *Hh = BP(__nv_bfloat16, O_HH),   *Hl = BP(__nv_bfloat16, O_HL);
    __nv_bfloat16 *WQKVh = BP(__nv_bfloat16, O_WQKVH), *WQKVl = BP(__nv_bfloat16, O_WQKVL);
    __nv_bfloat16 *WOh = BP(__nv_bfloat16, O_WOH), *WOl = BP(__nv_bfloat16, O_WOL);
    __nv_bfloat16 *W1h = BP(__nv_bfloat16, O_W1H), *W1l = BP(__nv_bfloat16, O_W1L);
    __nv_bfloat16 *W2h = BP(__nv_bfloat16, O_W2H), *W2l = BP(__nv_bfloat16, O_W2L);

    const __nv_bfloat16 *Qh = QKVh,          *Ql = QKVl;
    const __nv_bfloat16 *Kh = QKVh + 1024,   *Kl = QKVl + 1024;
    const __nv_bfloat16 *Vh = QKVh + 2048,   *Vl = QKVl + 2048;

    const int SMG  = 1024 + 4 * (256 + 512) * 64;   // 197632 (4 x 48KB) -> 1 CTA/SM
    const int SMFA = 232448;
    cudaFuncSetAttribute(mma_gemm<256, 0, 1>, cudaFuncAttributeMaxDynamicSharedMemorySize, SMG);
    cudaFuncSetAttribute(mma_gemm<256, 1, 0>, cudaFuncAttributeMaxDynamicSharedMemorySize, SMG);
    cudaFuncSetAttribute(mma_gemm<256, 2, 1>, cudaFuncAttributeMaxDynamicSharedMemorySize, SMG);
    cudaFuncSetAttribute(flash_attn_k, cudaFuncAttributeMaxDynamicSharedMemorySize, SMFA);

    // One-time side-stream setup (first call = uncaptured correctness run;
    // captured graph contains the same fork/join DAG every call).
    static cudaStream_t s2 = nullptr;
    static cudaEvent_t evFork = nullptr, evW4 = nullptr, evPrep = nullptr;
    if (s2 == nullptr) {
        cudaStreamCreateWithFlags(&s2, cudaStreamNonBlocking);
        cudaEventCreateWithFlags(&evFork, cudaEventDisableTiming);
        cudaEventCreateWithFlags(&evW4,   cudaEventDisableTiming);
        cudaEventCreateWithFlags(&evPrep, cudaEventDisableTiming);
    }

    const long long ZVT = (long long)DKH * SEQ;

    // fork: weight prep on s2 concurrent with main chain
    cudaEventRecord(evFork, 0);
    cudaStreamWaitEvent(s2, evFork, 0);
    w4_transpose_k<<<dim3(32, 32, 4), 256, 0, s2>>>(wq, wk, wv, wo, WQKVh, WQKVl, WOh, WOl);
    cudaEventRecord(evW4, s2);
    transpose_split_k<<<dim3(128, 32, 1), 256, 0, s2>>>(w1, W1h, W1l, 4096, 1024);
    transpose_split_k<<<dim3(32, 128, 1), 256, 0, s2>>>(w2, W2h, W2l, 1024, 4096);
    cudaEventRecord(evPrep, s2);

    // main chain
    split_k<<<(MTOK * DMODEL / 4 + 255) / 256, 256>>>((const float4*)x, Xh, Xl, MTOK * DMODEL / 4);
    cudaStreamWaitEvent(0, evW4, 0);
    mma_gemm<256, 0, 1><<<dim3(12, 32, 1), 256, SMG>>>(Xh, Xl, WQKVh, WQKVl, nullptr,
        nullptr, QKVh, QKVl, 1024, 1024, 1024, LDQKV, 1.0f);
    transpose_bf16_k<<<dim3(2, 64, 32), 256>>>(Vh, Vl, Vth, Vtl, LDQKV, SEQ,
        (long long)SEQ * LDQKV, 64, (long long)NHEADS * ZVT, ZVT, NHEADS);
    flash_attn_k<<<dim3(16, 32, 1), 256, SMFA>>>(Qh, Ql, Kh, Kl, Vth, Vtl, mask,
                                                 Cxh, Cxl, LDQKV);
    mma_gemm<256, 1, 0><<<dim3(4, 32, 1), 256, SMG>>>(Cxh, Cxl, WOh, WOl, wo_b,
        AO, nullptr, nullptr, 1024, 1024, 1024, 1024, 1.0f);
    add_ln_k<true><<<MTOK, 256>>>(x, AO, g1, be1, X1, X1h, X1l);
    cudaStreamWaitEvent(0, evPrep, 0);
    mma_gemm<256, 2, 1><<<dim3(16, 32, 1), 256, SMG>>>(X1h, X1l, W1h, W1l, b1,
        nullptr, Hh, Hl, 1024, 1024, 1024, 4096, 1.0f);
    mma_gemm<256, 1, 0><<<dim3(4, 32, 1), 256, SMG>>>(Hh, Hl, W2h, W2l, b2,
        FF, nullptr, nullptr, 4096, 4096, 4096, 1024, 1.0f);
    add_ln_k<false><<<MTOK, 256>>>(X1, FF, g2, be2, out, nullptr, nullptr);
}

// round 17
// speedup vs baseline: 1.5294x; 1.5294x over previous
#include <cuda_runtime.h>
#include <cuda_bf16.h>
#include <math.h>
#include <stdint.h>

#define DMODEL 1024
#define NHEADS 16
#define DKH    64
#define DFF    4096
#define BATCH  2
#define SEQ    2048
#define MTOK   (BATCH*SEQ)
#define LDQKV  3072

#if defined(__CUDA_ARCH__) && (defined(__CUDA_ARCH_FEAT_SM103_ALL) || defined(__CUDA_ARCH_FEAT_SM100_ALL))
#define HAS_TCGEN05 1
#else
#define HAS_TCGEN05 0
#endif

// ---------------------------------------------------------------- scratch
static const long long SZ_TBF  = 8388608LL;
static const long long SZ_QKV  = 25165824LL;
static const long long SZ_TF   = 16777216LL;
static const long long SZ_HBF  = 33554432LL;
static const long long SZ_WQKV = 6291456LL;
static const long long SZ_WBF  = 2097152LL;
static const long long SZ_WFBF = 8388608LL;

static const long long O_XH    = 0;
static const long long O_XL    = O_XH   + SZ_TBF;
static const long long O_QKVH  = O_XL   + SZ_TBF;
static const long long O_QKVL  = O_QKVH + SZ_QKV;
static const long long O_VTH   = O_QKVL + SZ_QKV;
static const long long O_VTL   = O_VTH  + SZ_TBF;
static const long long O_CH    = O_VTL  + SZ_TBF;
static const long long O_CL    = O_CH   + SZ_TBF;
static const long long O_X1H   = O_CL   + SZ_TBF;
static const long long O_X1L   = O_X1H  + SZ_TBF;
static const long long O_AO    = O_X1L  + SZ_TBF;
static const long long O_X1    = O_AO   + SZ_TF;
static const long long O_FF    = O_X1   + SZ_TF;
static const long long O_HH    = O_FF   + SZ_TF;
static const long long O_HL    = O_HH   + SZ_HBF;
static const long long O_WQKVH = O_HL   + SZ_HBF;
static const long long O_WQKVL = O_WQKVH + SZ_WQKV;
static const long long O_WOH   = O_WQKVL + SZ_WQKV;
static const long long O_WOL   = O_WOH  + SZ_WBF;
static const long long O_W1H   = O_WOL  + SZ_WBF;
static const long long O_W1L   = O_W1H  + SZ_WFBF;
static const long long O_W2H   = O_W1L  + SZ_WFBF;
static const long long O_W2L   = O_W2H  + SZ_WFBF;
static const long long TOTAL_BYTES = O_W2L + SZ_WFBF;

__device__ __align__(1024) unsigned char g_buf[TOTAL_BYTES];

// ---------------------------------------------------------------- helpers
__device__ __forceinline__ uint32_t smem_u32(const void* p) {
    uint32_t a;
    asm("{ .reg .u64 t; cvta.to.shared.u64 t, %1; cvt.u32.u64 %0, t; }"
        : "=r"(a) : "l"(p));
    return a;
}

__device__ __forceinline__ void mbar_wait(uint32_t addr, uint32_t parity) {
    asm volatile(
        "{\n\t.reg .pred P;\n\t"
        "W%=:\n\t"
        "mbarrier.try_wait.parity.acquire.cta.shared::cta.b64 P, [%0], %1;\n\t"
        "@!P bra W%=;\n\t}"
        :: "r"(addr), "r"(parity) : "memory");
}

static __device__ const unsigned long long DESC_BASE =
    (2ULL << 61) | (1ULL << 46) | (64ULL << 32) | (1ULL << 16);
static __device__ const unsigned long long DESC64_BASE =
    (4ULL << 61) | (1ULL << 46) | (32ULL << 32) | (1ULL << 16);

__device__ __forceinline__ unsigned long long dsc(uint32_t a) {
    return DESC_BASE | ((a >> 4) & 0x3FFF);
}
__device__ __forceinline__ unsigned long long dsc64(uint32_t a) {
    return DESC64_BASE | ((a >> 4) & 0x3FFF);
}

template<int BN> __device__ __forceinline__ uint32_t idesc_v() {
    return (1u << 4) | (1u << 7) | (1u << 10) | ((uint32_t)(BN / 8) << 17) | (8u << 24);
}

__device__ __forceinline__ float gelu_exact(float v) {
    return 0.5f * v * (1.0f + erff(v * 0.70710678118654752f));
}

__device__ __forceinline__ void split2(float v, __nv_bfloat16& h, __nv_bfloat16& l) {
    h = __float2bfloat16(v);
    l = __float2bfloat16(v - __bfloat162float(h));
}

#if HAS_TCGEN05
__device__ __forceinline__ void tc_mma(uint32_t d, unsigned long long ad,
                                       unsigned long long bd, uint32_t idesc, uint32_t en) {
    asm volatile(
        "{\n\t.reg .pred p;\n\tsetp.ne.u32 p, %4, 0;\n\t"
        "tcgen05.mma.cta_group::1.kind::f16 [%0], %1, %2, %3, {%5,%5,%5,%5}, p;\n\t}"
        :: "r"(d), "l"(ad), "l"(bd), "r"(idesc), "r"(en), "r"(0u) : "memory");
}
__device__ __forceinline__ void tc_commit(uint32_t mbar) {
    asm volatile(
        "tcgen05.commit.cta_group::1.mbarrier::arrive::one.shared::cluster.b64 [%0];"
        :: "r"(mbar) : "memory");
}
#define LDTM_X32(r, a)                                                         \
    asm volatile(                                                              \
        "tcgen05.ld.sync.aligned.32x32b.x32.b32 "                              \
        "{%0,%1,%2,%3,%4,%5,%6,%7,%8,%9,%10,%11,%12,%13,%14,%15,"              \
        "%16,%17,%18,%19,%20,%21,%22,%23,%24,%25,%26,%27,%28,%29,%30,%31}, [%32];" \
        : "=r"((r)[0]),  "=r"((r)[1]),  "=r"((r)[2]),  "=r"((r)[3]),           \
          "=r"((r)[4]),  "=r"((r)[5]),  "=r"((r)[6]),  "=r"((r)[7]),           \
          "=r"((r)[8]),  "=r"((r)[9]),  "=r"((r)[10]), "=r"((r)[11]),          \
          "=r"((r)[12]), "=r"((r)[13]), "=r"((r)[14]), "=r"((r)[15]),          \
          "=r"((r)[16]), "=r"((r)[17]), "=r"((r)[18]), "=r"((r)[19]),          \
          "=r"((r)[20]), "=r"((r)[21]), "=r"((r)[22]), "=r"((r)[23]),          \
          "=r"((r)[24]), "=r"((r)[25]), "=r"((r)[26]), "=r"((r)[27]),          \
          "=r"((r)[28]), "=r"((r)[29]), "=r"((r)[30]), "=r"((r)[31])           \
        : "r"(a))
#define STTM_X32(a, r)                                                         \
    asm volatile(                                                              \
        "tcgen05.st.sync.aligned.32x32b.x32.b32 [%0], "                        \
        "{%1,%2,%3,%4,%5,%6,%7,%8,%9,%10,%11,%12,%13,%14,%15,%16,"             \
        "%17,%18,%19,%20,%21,%22,%23,%24,%25,%26,%27,%28,%29,%30,%31,%32};"    \
        :: "r"(a),                                                             \
           "r"((r)[0]),  "r"((r)[1]),  "r"((r)[2]),  "r"((r)[3]),              \
           "r"((r)[4]),  "r"((r)[5]),  "r"((r)[6]),  "r"((r)[7]),              \
           "r"((r)[8]),  "r"((r)[9]),  "r"((r)[10]), "r"((r)[11]),             \
           "r"((r)[12]), "r"((r)[13]), "r"((r)[14]), "r"((r)[15]),             \
           "r"((r)[16]), "r"((r)[17]), "r"((r)[18]), "r"((r)[19]),             \
           "r"((r)[20]), "r"((r)[21]), "r"((r)[22]), "r"((r)[23]),             \
           "r"((r)[24]), "r"((r)[25]), "r"((r)[26]), "r"((r)[27]),             \
           "r"((r)[28]), "r"((r)[29]), "r"((r)[30]), "r"((r)[31])              \
        : "memory")
#endif

// SW128 tile loader (128B rows) — flash
template<int ROWS>
__device__ __forceinline__ void cp_tile(uint32_t dst, const __nv_bfloat16* __restrict__ src,
                                        int ldsrc, int tid)
{
#pragma unroll
    for (int i = 0; i < ROWS / 32; ++i) {
        int idx = tid + i * 256;
        int r = idx >> 3, kb = (idx & 7) * 16;
        uint32_t off = (uint32_t)(r * 128 + kb);
        off ^= (off >> 3) & 0x70;
        asm volatile("cp.async.cg.shared.global [%0], [%1], 16;"
                     :: "r"(dst + off), "l"((const char*)(src + (long long)r * ldsrc) + kb));
    }
}

// SW64 tile loader (64B rows) — GEMM, K-chunk 32
template<int ROWS>
__device__ __forceinline__ void cp_tile64(uint32_t dst, const __nv_bfloat16* __restrict__ src,
                                          int ldsrc, int tid)
{
#pragma unroll
    for (int i = 0; i < ROWS / 64; ++i) {
        int idx = tid + i * 256;
        int r = idx >> 2, kb = (idx & 3) * 16;
        uint32_t off = (uint32_t)(r * 64 + kb);
        off ^= (off >> 3) & 0x30;
        asm volatile("cp.async.cg.shared.global [%0], [%1], 16;"
                     :: "r"(dst + off), "l"((const char*)(src + (long long)r * ldsrc) + kb));
    }
}

// ---------------------------------------------------------------- tcgen05 GEMM (R14 exact: 4-stage, 1 CTA/SM)
template<int BN, int EPI, int OUT>
__global__ __launch_bounds__(256)
void mma_gemm(const __nv_bfloat16* __restrict__ Ah, const __nv_bfloat16* __restrict__ Al,
              const __nv_bfloat16* __restrict__ Bh, const __nv_bfloat16* __restrict__ Bl,
              const float* __restrict__ bias,
              float* __restrict__ C, __nv_bfloat16* __restrict__ Ch, __nv_bfloat16* __restrict__ Cl,
              int K, int lda, int ldb, int ldc, float alpha)
{
#if HAS_TCGEN05
    constexpr uint32_t T_AL = 8192;
    constexpr uint32_t T_BH = 16384;
    constexpr uint32_t T_BL = 16384 + BN * 64;
    constexpr uint32_t SS   = (256 + 2 * BN) * 64;   // 48KB

    extern __shared__ unsigned char smraw[];
    const uint32_t smb  = smem_u32(smraw);
    const uint32_t MBAR = smb + 8;
    const uint32_t ST0  = smb + 1024;

    const int tid = threadIdx.x, wid = tid >> 5, lane = tid & 31;
    const int m0 = blockIdx.y * 128;
    const int n0 = blockIdx.x * BN;

    if (wid == 0) {
        asm volatile("tcgen05.alloc.cta_group::1.sync.aligned.shared::cta.b32 [%0], %1;"
                     :: "r"(smb), "r"((uint32_t)BN) : "memory");
        asm volatile("tcgen05.relinquish_alloc_permit.cta_group::1.sync.aligned;");
    }
    if (tid == 0)
        asm volatile("mbarrier.init.shared.b64 [%0], 1;" :: "r"(MBAR) : "memory");
    __syncthreads();
    uint32_t tmem;
    asm volatile("ld.shared.b32 %0, [%1];" : "=r"(tmem) : "r"(smb));

    const __nv_bfloat16* Ap  = Ah + (long long)m0 * lda;
    const __nv_bfloat16* Alp = Al + (long long)m0 * lda;
    const __nv_bfloat16* Bp  = Bh + (long long)n0 * ldb;
    const __nv_bfloat16* Blp = Bl + (long long)n0 * ldb;

    const int nch = K >> 5;

    // prologue: chunks 0..2 into stages 0..2
#pragma unroll
    for (int t = 0; t < 3; ++t) {
        const uint32_t st = ST0 + t * SS;
        const int k0 = t << 5;
        cp_tile64<128>(st,        Ap  + k0, lda, tid);
        cp_tile64<128>(st + T_AL, Alp + k0, lda, tid);
        cp_tile64<BN >(st + T_BH, Bp  + k0, ldb, tid);
        cp_tile64<BN >(st + T_BL, Blp + k0, ldb, tid);
        asm volatile("cp.async.commit_group;" ::: "memory");
    }

    for (int c = 0; c < nch; ++c) {
        const int rem = nch - 1 - c;
        if (rem >= 2)      asm volatile("cp.async.wait_group 2;" ::: "memory");
        else if (rem == 1) asm volatile("cp.async.wait_group 1;" ::: "memory");
        else               asm volatile("cp.async.wait_group 0;" ::: "memory");
        __syncthreads();
        asm volatile("fence.proxy.async.shared::cta;" ::: "memory");
        if (tid == 0) {
            const uint32_t st = ST0 + (uint32_t)(c & 3) * SS;
            const uint32_t ao[3] = {st, st, st + T_AL};
            const uint32_t bo[3] = {st + T_BH, st + T_BL, st + T_BH};
#pragma unroll
            for (int p = 0; p < 3; ++p) {
                unsigned long long ad = dsc64(ao[p]);
                unsigned long long bd = dsc64(bo[p]);
#pragma unroll
                for (int s = 0; s < 2; ++s) {
                    uint32_t en = (c > 0 || p > 0 || s > 0) ? 1u : 0u;
                    tc_mma(tmem, ad + s * 2, bd + s * 2, idesc_v<BN>(), en);
                }
            }
        }
        if (c > 0) mbar_wait(MBAR, (uint32_t)((c - 1) & 1));
        if (tid == 0) tc_commit(MBAR);
        if (c + 3 < nch) {
            const uint32_t st = ST0 + (uint32_t)((c + 3) & 3) * SS;
            const int k0 = (c + 3) << 5;
            cp_tile64<128>(st,        Ap  + k0, lda, tid);
            cp_tile64<128>(st + T_AL, Alp + k0, lda, tid);
            cp_tile64<BN >(st + T_BH, Bp  + k0, ldb, tid);
            cp_tile64<BN >(st + T_BL, Blp + k0, ldb, tid);
            asm volatile("cp.async.commit_group;" ::: "memory");
        }
    }
    mbar_wait(MBAR, (uint32_t)((nch - 1) & 1));
    asm volatile("tcgen05.fence::after_thread_sync;" ::: "memory");

    const int half = wid >> 2;
    const int m = m0 + (wid & 3) * 32 + lane;
    const int colBase = half * (BN / 2);
#pragma unroll
    for (int c0 = 0; c0 < BN / 2; c0 += 32) {
        uint32_t r[32];
        LDTM_X32(r, tmem + colBase + c0);
        asm volatile("tcgen05.wait::ld.sync.aligned;" ::: "memory");

#pragma unroll
        for (int j = 0; j < 32; j += 4) {
            float v[4];
#pragma unroll
            for (int q = 0; q < 4; ++q) {
                float t = __uint_as_float(r[j + q]) * alpha;
                if (EPI >= 1) t += bias[n0 + colBase + c0 + j + q];
                if (EPI == 2) t = gelu_exact(t);
                v[q] = t;
            }
            const long long cix = (long long)m * ldc + n0 + colBase + c0 + j;
            if (OUT == 0) {
                float4 o; o.x = v[0]; o.y = v[1]; o.z = v[2]; o.w = v[3];
                *(float4*)(C + cix) = o;
            } else {
                __nv_bfloat16 h[4], l[4];
#pragma unroll
                for (int q = 0; q < 4; ++q) split2(v[q], h[q], l[q]);
                uint2 uh, ul;
                uh.x = ((uint32_t)__bfloat16_as_ushort(h[1]) << 16) | __bfloat16_as_ushort(h[0]);
                uh.y = ((uint32_t)__bfloat16_as_ushort(h[3]) << 16) | __bfloat16_as_ushort(h[2]);
                ul.x = ((uint32_t)__bfloat16_as_ushort(l[1]) << 16) | __bfloat16_as_ushort(l[0]);
                ul.y = ((uint32_t)__bfloat16_as_ushort(l[3]) << 16) | __bfloat16_as_ushort(l[2]);
                *(uint2*)(Ch + cix) = uh;
                *(uint2*)(Cl + cix) = ul;
            }
        }
    }

    __syncthreads();
    if (wid == 0)
        asm volatile("tcgen05.dealloc.cta_group::1.sync.aligned.b32 %0, %1;"
                     :: "r"(tmem), "r"((uint32_t)BN));
#else
    __trap();
#endif
}

// ---------------------------------------------------------------- flash attention (R14 exact)
#if HAS_TCGEN05
__device__ __forceinline__ void issue_smma(uint32_t tmem, uint32_t qh, uint32_t ql, uint32_t st) {
    const uint32_t aT[3] = {qh, qh, ql};
    const uint32_t bT[3] = {st, st + 16384, st};
#pragma unroll
    for (int p = 0; p < 3; ++p) {
        unsigned long long ad = dsc(aT[p]);
        unsigned long long bd = dsc(bT[p]);
#pragma unroll
        for (int s = 0; s < 4; ++s)
            tc_mma(tmem + 64, ad + s * 2, bd + s * 2, idesc_v<128>(),
                   (p > 0 || s > 0) ? 1u : 0u);
    }
}

__device__ __forceinline__ void issue_pv(uint32_t tmem, uint32_t ph, uint32_t pl,
                                         uint32_t st, int first) {
    const uint32_t aT[3] = {ph, ph, pl};
    const uint32_t bT[3] = {st + 32768, st + 49152, st + 32768};
#pragma unroll
    for (int p = 0; p < 3; ++p)
#pragma unroll
        for (int c = 0; c < 2; ++c) {
            unsigned long long ad = dsc(aT[p] + c * 16384);
            unsigned long long bd = dsc(bT[p] + c * 8192);
#pragma unroll
            for (int s = 0; s < 4; ++s)
                tc_mma(tmem, ad + s * 2, bd + s * 2, idesc_v<64>(),
                       (first && p == 0 && c == 0 && s == 0) ? 0u : 1u);
        }
}
#endif

__global__ __launch_bounds__(256)
void flash_attn_k(const __nv_bfloat16* __restrict__ Qh, const __nv_bfloat16* __restrict__ Ql,
                  const __nv_bfloat16* __restrict__ Kh, const __nv_bfloat16* __restrict__ Kl,
                  const __nv_bfloat16* __restrict__ Vth, const __nv_bfloat16* __restrict__ Vtl,
                  const int* __restrict__ mask,
                  __nv_bfloat16* __restrict__ Ch, __nv_bfloat16* __restrict__ Cl, int ldq)
{
#if HAS_TCGEN05
    extern __shared__ unsigned char smraw[];
    const uint32_t smb  = smem_u32(smraw);
    const uint32_t SBAR = smb + 8;
    const uint32_t PBAR = smb + 16;
    float* biasS  = (float*)(smraw + 512);
    float* redMax = (float*)(smraw + 1024);
    float* redSum = (float*)(smraw + 2048);
    const uint32_t SM_QH = smb + 3072,  SM_QL = SM_QH + 16384;
    const uint32_t SM_PH = smb + 35840, SM_PL = SM_PH + 32768;
    const uint32_t ST0   = smb + 101376;
    constexpr uint32_t STS_ = 65536;

    const int tid = threadIdx.x, wid = tid >> 5, lane = tid & 31;
    const int sub = wid & 3;
    const int colh = wid >> 2;
    const int rowP = sub * 32 + lane;
    const int qt = blockIdx.x, bh = blockIdx.y, b = bh >> 4, h = bh & 15;

    const long long qoff  = ((long long)(b * SEQ + qt * 128)) * ldq + h * 64;
    const long long kbase = (long long)b * SEQ * ldq + h * 64;
    const long long vbase = (long long)bh * (64LL * SEQ);

    if (wid == 0) {
        asm volatile("tcgen05.alloc.cta_group::1.sync.aligned.shared::cta.b32 [%0], %1;"
                     :: "r"(smb), "r"(256u) : "memory");
        asm volatile("tcgen05.relinquish_alloc_permit.cta_group::1.sync.aligned;");
    }
    if (tid == 0) {
        asm volatile("mbarrier.init.shared.b64 [%0], 1;" :: "r"(SBAR) : "memory");
        asm volatile("mbarrier.init.shared.b64 [%0], 1;" :: "r"(PBAR) : "memory");
    }
    __syncthreads();
    uint32_t tmem;
    asm volatile("ld.shared.b32 %0, [%1];" : "=r"(tmem) : "r"(smb));

    cp_tile<128>(SM_QH, Qh + qoff, ldq, tid);
    cp_tile<128>(SM_QL, Ql + qoff, ldq, tid);
#pragma unroll
    for (int t = 0; t < 2; ++t) {
        const uint32_t st = ST0 + t * STS_;
        const long long ko = kbase + (long long)t * 128 * ldq;
        const long long vo = vbase + t * 128;
        cp_tile<128>(st,         Kh  + ko, ldq, tid);
        cp_tile<128>(st + 16384, Kl  + ko, ldq, tid);
        cp_tile<64>(st + 32768,  Vth + vo,      SEQ, tid);
        cp_tile<64>(st + 40960,  Vth + vo + 64, SEQ, tid);
        cp_tile<64>(st + 49152,  Vtl + vo,      SEQ, tid);
        cp_tile<64>(st + 57344,  Vtl + vo + 64, SEQ, tid);
        asm volatile("cp.async.commit_group;" ::: "memory");
    }
    asm volatile("cp.async.wait_group 1;" ::: "memory");
    __syncthreads();
    asm volatile("fence.proxy.async.shared::cta;" ::: "memory");
    if (tid == 0) {
        asm volatile("tcgen05.fence::after_thread_sync;" ::: "memory");
        issue_smma(tmem, SM_QH, SM_QL, ST0);
        tc_commit(SBAR);
    }

    float mold = -3.4e38f, lrun = 0.0f;
    int sPh = 0, pPh = 0;

    for (int i = 0; i < 16; ++i) {
        mbar_wait(SBAR, (uint32_t)(sPh & 1)); ++sPh;
        asm volatile("tcgen05.fence::after_thread_sync;" ::: "memory");

        if (i >= 1 && i < 15) {
            const uint32_t st = ST0 + (((i + 1) & 1) ? STS_ : 0u);
            const long long ko = kbase + (long long)(i + 1) * 128 * ldq;
            cp_tile<128>(st,         Kh + ko, ldq, tid);
            cp_tile<128>(st + 16384, Kl + ko, ldq, tid);
            asm volatile("cp.async.commit_group;" ::: "memory");
        }
        if (tid < 128)
            biasS[tid] = (mask[b * SEQ + i * 128 + tid] == 0) ? -1e9f : 0.0f;
        __syncthreads();

        float sv[64];
        {
            uint32_t r[32];
#pragma unroll
            for (int g = 0; g < 2; ++g) {
                LDTM_X32(r, tmem + 64 + colh * 64 + g * 32);
                asm volatile("tcgen05.wait::ld.sync.aligned;" ::: "memory");
#pragma unroll
                for (int j = 0; j < 32; ++j) sv[g * 32 + j] = __uint_as_float(r[j]);
            }
        }
        asm volatile("tcgen05.fence::before_thread_sync;" ::: "memory");

        if (i + 1 < 16) {
            asm volatile("cp.async.wait_group 0;" ::: "memory");
            __syncthreads();
            asm volatile("fence.proxy.async.shared::cta;" ::: "memory");
            if (tid == 0) {
                asm volatile("tcgen05.fence::after_thread_sync;" ::: "memory");
                issue_smma(tmem, SM_QH, SM_QL, ST0 + (((i + 1) & 1) ? STS_ : 0u));
                tc_commit(SBAR);
            }
        } else {
            asm volatile("cp.async.wait_group 0;" ::: "memory");
            __syncthreads();
        }

        float pmax = -3.4e38f;
#pragma unroll
        for (int j = 0; j < 64; ++j) {
            float s = sv[j] * 0.125f + biasS[colh * 64 + j];
            sv[j] = s;
            pmax = fmaxf(pmax, s);
        }
        redMax[colh * 128 + rowP] = pmax;
        __syncthreads();
        const float mnew = fmaxf(mold, fmaxf(redMax[rowP], redMax[128 + rowP]));
        const float alpha = __expf(mold - mnew);

        if (i > 0) {
            mbar_wait(PBAR, (uint32_t)(pPh & 1)); ++pPh;
            asm volatile("tcgen05.fence::after_thread_sync;" ::: "memory");
            if (__any_sync(0xffffffffu, mnew != mold)) {
                uint32_t r[32];
                LDTM_X32(r, tmem + colh * 32);
                asm volatile("tcgen05.wait::ld.sync.aligned;" ::: "memory");
#pragma unroll
                for (int j = 0; j < 32; ++j)
                    r[j] = __float_as_uint(__uint_as_float(r[j]) * alpha);
                STTM_X32(tmem + ((uint32_t)sub << 21) + colh * 32, r);
                asm volatile("tcgen05.wait::st.sync.aligned;" ::: "memory");
            }
            if (i < 15) {
                const uint32_t st = ST0 + (((i + 1) & 1) ? STS_ : 0u);
                const long long vo = vbase + (long long)(i + 1) * 128;
                cp_tile<64>(st + 32768, Vth + vo,      SEQ, tid);
                cp_tile<64>(st + 40960, Vth + vo + 64, SEQ, tid);
                cp_tile<64>(st + 49152, Vtl + vo,      SEQ, tid);
                cp_tile<64>(st + 57344, Vtl + vo + 64, SEQ, tid);
                asm volatile("cp.async.commit_group;" ::: "memory");
            }
        }
        mold = mnew;

        float ls = 0.0f;
#pragma unroll
        for (int j = 0; j < 64; ++j) {
            float p = __expf(sv[j] - mnew);
            sv[j] = p;
            ls += p;
        }
        redSum[colh * 128 + rowP] = ls;

        {
            const uint32_t baseH = SM_PH + colh * 16384;
            const uint32_t baseL = SM_PL + colh * 16384;
#pragma unroll
            for (int j0 = 0; j0 < 64; j0 += 8) {
                uint32_t hw[4], lw[4];
#pragma unroll
                for (int q = 0; q < 4; ++q) {
                    float v0 = sv[j0 + 2 * q], v1 = sv[j0 + 2 * q + 1];
                    __nv_bfloat16 h0, l0, h1, l1;
                    split2(v0, h0, l0); split2(v1, h1, l1);
                    hw[q] = ((uint32_t)__bfloat16_as_ushort(h1) << 16) | __bfloat16_as_ushort(h0);
                    lw[q] = ((uint32_t)__bfloat16_as_ushort(l1) << 16) | __bfloat16_as_ushort(l0);
                }
                uint32_t off = (uint32_t)(rowP * 128 + j0 * 2);
                off ^= (off >> 3) & 0x70;
                asm volatile("st.shared.v4.b32 [%0], {%1,%2,%3,%4};"
                             :: "r"(baseH + off), "r"(hw[0]), "r"(hw[1]), "r"(hw[2]), "r"(hw[3]));
                asm volatile("st.shared.v4.b32 [%0], {%1,%2,%3,%4};"
                             :: "r"(baseL + off), "r"(lw[0]), "r"(lw[1]), "r"(lw[2]), "r"(lw[3]));
            }
        }
        asm volatile("tcgen05.fence::before_thread_sync;" ::: "memory");
        asm volatile("fence.proxy.async.shared::cta;" ::: "memory");
        __syncthreads();
        lrun = lrun * alpha + redSum[rowP] + redSum[128 + rowP];
        if (tid == 0) {
            asm volatile("tcgen05.fence::after_thread_sync;" ::: "memory");
            issue_pv(tmem, SM_PH, SM_PL, ST0 + ((i & 1) ? STS_ : 0u), i == 0);
            tc_commit(PBAR);
        }
    }

    mbar_wait(PBAR, (uint32_t)(pPh & 1)); ++pPh;
    asm volatile("tcgen05.fence::after_thread_sync;" ::: "memory");

    {
        uint32_t r[32];
        LDTM_X32(r, tmem + colh * 32);
        asm volatile("tcgen05.wait::ld.sync.aligned;" ::: "memory");
        asm volatile("tcgen05.fence::before_thread_sync;" ::: "memory");
        const float inv = 1.0f / lrun;
        const long long row = (long long)b * SEQ + qt * 128 + rowP;
        const long long cix = row * DMODEL + h * 64 + colh * 32;
#pragma unroll
        for (int j = 0; j < 32; j += 4) {
            __nv_bfloat16 hh[4], ll[4];
#pragma unroll
            for (int q = 0; q < 4; ++q) {
                float v = __uint_as_float(r[j + q]) * inv;
                split2(v, hh[q], ll[q]);
            }
            uint2 uh, ul;
            uh.x = ((uint32_t)__bfloat16_as_ushort(hh[1]) << 16) | __bfloat16_as_ushort(hh[0]);
            uh.y = ((uint32_t)__bfloat16_as_ushort(hh[3]) << 16) | __bfloat16_as_ushort(hh[2]);
            ul.x = ((uint32_t)__bfloat16_as_ushort(ll[1]) << 16) | __bfloat16_as_ushort(ll[0]);
            ul.y = ((uint32_t)__bfloat16_as_ushort(ll[3]) << 16) | __bfloat16_as_ushort(ll[2]);
            *(uint2*)(Ch + cix + j) = uh;
            *(uint2*)(Cl + cix + j) = ul;
        }
    }
    __syncthreads();
    if (wid == 0)
        asm volatile("tcgen05.dealloc.cta_group::1.sync.aligned.b32 %0, %1;"
                     :: "r"(tmem), "r"(256u));
#else
    __trap();
#endif
}

// ---------------------------------------------------------------- prep kernels
__global__ __launch_bounds__(256)
void split_k(const float4* __restrict__ in, __nv_bfloat16* __restrict__ oh,
             __nv_bfloat16* __restrict__ ol, int n4)
{
    int i = blockIdx.x * 256 + threadIdx.x;
    if (i >= n4) return;
    float4 v = in[i];
    __nv_bfloat16 h[4], l[4];
    split2(v.x, h[0], l[0]); split2(v.y, h[1], l[1]);
    split2(v.z, h[2], l[2]); split2(v.w, h[3], l[3]);
    uint2 uh, ul;
    uh.x = ((uint32_t)__bfloat16_as_ushort(h[1]) << 16) | __bfloat16_as_ushort(h[0]);
    uh.y = ((uint32_t)__bfloat16_as_ushort(h[3]) << 16) | __bfloat16_as_ushort(h[2]);
    ul.x = ((uint32_t)__bfloat16_as_ushort(l[1]) << 16) | __bfloat16_as_ushort(l[0]);
    ul.y = ((uint32_t)__bfloat16_as_ushort(l[3]) << 16) | __bfloat16_as_ushort(l[2]);
    ((uint2*)oh)[i] = uh;
    ((uint2*)ol)[i] = ul;
}

__global__ __launch_bounds__(256)
void transpose_split_k(const float* __restrict__ in, __nv_bfloat16* __restrict__ oh,
                       __nv_bfloat16* __restrict__ ol, int ldin, int ldout)
{
    __shared__ float t[32][33];
    const int c0 = blockIdx.x * 32, r0 = blockIdx.y * 32;
    const int tx = threadIdx.x & 31, ty = threadIdx.x >> 5;
#pragma unroll
    for (int i = 0; i < 32; i += 8)
        t[ty + i][tx] = in[(long long)(r0 + ty + i) * ldin + c0 + tx];
    __syncthreads();
#pragma unroll
    for (int i = 0; i < 32; i += 8) {
        float v = t[tx][ty + i];
        __nv_bfloat16 h, l; split2(v, h, l);
        long long o = (long long)(c0 + ty + i) * ldout + r0 + tx;
        oh[o] = h; ol[o] = l;
    }
}

__global__ __launch_bounds__(256)
void w4_transpose_k(const float* __restrict__ wq, const float* __restrict__ wk,
                    const float* __restrict__ wv, const float* __restrict__ wo,
                    __nv_bfloat16* __restrict__ qkvh, __nv_bfloat16* __restrict__ qkvl,
                    __nv_bfloat16* __restrict__ woh, __nv_bfloat16* __restrict__ wol)
{
    __shared__ float t[32][33];
    const int z = blockIdx.z;
    const float* in = (z == 0) ? wq : (z == 1) ? wk : (z == 2) ? wv : wo;
    __nv_bfloat16* oh = (z < 3) ? qkvh + (long long)z * 1048576 : woh;
    __nv_bfloat16* ol = (z < 3) ? qkvl + (long long)z * 1048576 : wol;
    const int c0 = blockIdx.x * 32, r0 = blockIdx.y * 32;
    const int tx = threadIdx.x & 31, ty = threadIdx.x >> 5;
#pragma unroll
    for (int i = 0; i < 32; i += 8)
        t[ty + i][tx] = in[(long long)(r0 + ty + i) * 1024 + c0 + tx];
    __syncthreads();
#pragma unroll
    for (int i = 0; i < 32; i += 8) {
        float v = t[tx][ty + i];
        __nv_bfloat16 h, l; split2(v, h, l);
        long long o = (long long)(c0 + ty + i) * 1024 + r0 + tx;
        oh[o] = h; ol[o] = l;
    }
}

__global__ __launch_bounds__(256)
void transpose_bf16_k(const __nv_bfloat16* __restrict__ ih, const __nv_bfloat16* __restrict__ il,
                      __nv_bfloat16* __restrict__ oh, __nv_bfloat16* __restrict__ ol,
                      int ldin, int ldout,
                      long long iB, long long iH, long long oB, long long oH, int nH)
{
    __shared__ unsigned short th[32][33], tl[32][33];
    const int z = blockIdx.z, zb = z / nH, zh = z - zb * nH;
    ih += (long long)zb * iB + (long long)zh * iH;
    il += (long long)zb * iB + (long long)zh * iH;
    const long long oo = (long long)zb * oB + (long long)zh * oH;
    const int c0 = blockIdx.x * 32, r0 = blockIdx.y * 32;
    const int tx = threadIdx.x & 31, ty = threadIdx.x >> 5;
#pragma unroll
    for (int i = 0; i < 32; i += 8) {
        long long ix = (long long)(r0 + ty + i) * ldin + c0 + tx;
        th[ty + i][tx] = __bfloat16_as_ushort(ih[ix]);
        tl[ty + i][tx] = __bfloat16_as_ushort(il[ix]);
    }
    __syncthreads();
#pragma unroll
    for (int i = 0; i < 32; i += 8) {
        long long o = oo + (long long)(c0 + ty + i) * ldout + r0 + tx;
        oh[o] = __ushort_as_bfloat16(th[tx][ty + i]);
        ol[o] = __ushort_as_bfloat16(tl[tx][ty + i]);
    }
}

// residual + LN with warp-shuffle reductions (2 barriers instead of 16)
template<bool SPLIT>
__global__ __launch_bounds__(256)
void add_ln_k(const float* __restrict__ a, const float* __restrict__ rres,
              const float* __restrict__ g, const float* __restrict__ be,
              float* __restrict__ out, __nv_bfloat16* __restrict__ oh,
              __nv_bfloat16* __restrict__ ol)
{
    const long long row = blockIdx.x;
    const float* pa = a + row * DMODEL;
    const float* pr = rres + row * DMODEL;
    const int t = threadIdx.x, wid = t >> 5, lane = t & 31;
    constexpr int PER = DMODEL / 256;

    float v[PER];
    float s = 0.0f, s2 = 0.0f;
#pragma unroll
    for (int i = 0; i < PER; i++) {
        int c = t + i * 256;
        float x = pa[c] + pr[c];
        v[i] = x; s += x; s2 += x * x;
    }
#pragma unroll
    for (int o = 16; o > 0; o >>= 1) {
        s  += __shfl_xor_sync(0xffffffffu, s,  o);
        s2 += __shfl_xor_sync(0xffffffffu, s2, o);
    }
    __shared__ float w1s[8], w2s[8], bc[2];
    if (lane == 0) { w1s[wid] = s; w2s[wid] = s2; }
    __syncthreads();
    if (t == 0) {
        float ts = 0.0f, ts2 = 0.0f;
#pragma unroll
        for (int i = 0; i < 8; ++i) { ts += w1s[i]; ts2 += w2s[i]; }
        const float mu  = ts * (1.0f / DMODEL);
        const float var = ts2 * (1.0f / DMODEL) - mu * mu;
        bc[0] = mu;
        bc[1] = rsqrtf(var + 1e-6f);
    }
    __syncthreads();
    const float mu = bc[0], inv = bc[1];
#pragma unroll
    for (int i = 0; i < PER; i++) {
        int c = t + i * 256;
        float y = (v[i] - mu) * inv * g[c] + be[c];
        out[row * DMODEL + c] = y;
        if (SPLIT) {
            __nv_bfloat16 h, l; split2(y, h, l);
            oh[row * DMODEL + c] = h;
            ol[row * DMODEL + c] = l;
        }
    }
}

// ---------------------------------------------------------------- launch
extern "C" void kernel_launch(void* const* d_in, const int* in_sizes, int n_in,
                              void* d_out, int out_size)
{
    const float* x    = (const float*)d_in[0];
    const int*   mask = (const int*)  d_in[1];
    const float* wq   = (const float*)d_in[2];
    const float* wk   = (const float*)d_in[3];
    const float* wv   = (const float*)d_in[4];
    const float* wo   = (const float*)d_in[5];
    const float* wo_b = (const float*)d_in[6];
    const float* w1   = (const float*)d_in[7];
    const float* b1   = (const float*)d_in[8];
    const float* w2   = (const float*)d_in[9];
    const float* b2   = (const float*)d_in[10];
    const float* g1   = (const float*)d_in[11];
    const float* be1  = (const float*)d_in[12];
    const float* g2   = (const float*)d_in[13];
    const float* be2  = (const float*)d_in[14];
    float* out = (float*)d_out;

    unsigned char* gb = nullptr;
    cudaGetSymbolAddress((void**)&gb, g_buf);
#define BP(T, off) ((T*)(gb + (off)))
    __nv_bfloat16 *Xh = BP(__nv_bfloat16, O_XH),   *Xl = BP(__nv_bfloat16, O_XL);
    __nv_bfloat16 *QKVh = BP(__nv_bfloat16, O_QKVH), *QKVl = BP(__nv_bfloat16, O_QKVL);
    __nv_bfloat16 *Vth = BP(__nv_bfloat16, O_VTH), *Vtl = BP(__nv_bfloat16, O_VTL);
    __nv_bfloat16 *Cxh = BP(__nv_bfloat16, O_CH),  *Cxl = BP(__nv_bfloat16, O_CL);
    __nv_bfloat16 *X1h = BP(__nv_bfloat16, O_X1H), *X1l = BP(__nv_bfloat16, O_X1L);
    float *AO = BP(float, O_AO), *X1 = BP(float, O_X1), *FF = BP(float, O_FF);
    __nv_bfloat16 *Hh = BP(__nv_bfloat16, O_HH),   *Hl = BP(__nv_bfloat16, O_HL);
    __nv_bfloat16 *WQKVh = BP(__nv_bfloat16, O_WQKVH), *WQKVl = BP(__nv_bfloat16, O_WQKVL);
    __nv_bfloat16 *WOh = BP(__nv_bfloat16, O_WOH), *WOl = BP(__nv_bfloat16, O_WOL);
    __nv_bfloat16 *W1h = BP(__nv_bfloat16, O_W1H), *W1l = BP(__nv_bfloat16, O_W1L);
    __nv_bfloat16 *W2h = BP(__nv_bfloat16, O_W2H), *W2l = BP(__nv_bfloat16, O_W2L);

    const __nv_bfloat16 *Qh = QKVh,          *Ql = QKVl;
    const __nv_bfloat16 *Kh = QKVh + 1024,   *Kl = QKVl + 1024;
    const __nv_bfloat16 *Vh = QKVh + 2048,   *Vl = QKVl + 2048;

    const int SMG  = 1024 + 4 * (256 + 512) * 64;   // 197632 (4 x 48KB) -> 1 CTA/SM
    const int SMFA = 232448;
    cudaFuncSetAttribute(mma_gemm<256, 0, 1>, cudaFuncAttributeMaxDynamicSharedMemorySize, SMG);
    cudaFuncSetAttribute(mma_gemm<256, 1, 0>, cudaFuncAttributeMaxDynamicSharedMemorySize, SMG);
    cudaFuncSetAttribute(mma_gemm<256, 2, 1>, cudaFuncAttributeMaxDynamicSharedMemorySize, SMG);
    cudaFuncSetAttribute(flash_attn_k, cudaFuncAttributeMaxDynamicSharedMemorySize, SMFA);

    const long long ZVT = (long long)DKH * SEQ;

    // single stream, R14 launch order (QKV GEMM at ncu -s 5)
    split_k<<<(MTOK * DMODEL / 4 + 255) / 256, 256>>>((const float4*)x, Xh, Xl, MTOK * DMODEL / 4);
    w4_transpose_k<<<dim3(32, 32, 4), 256>>>(wq, wk, wv, wo, WQKVh, WQKVl, WOh, WOl);
    transpose_split_k<<<dim3(128, 32, 1), 256>>>(w1, W1h, W1l, 4096, 1024);
    mma_gemm<256, 0, 1><<<dim3(12, 32, 1), 256, SMG>>>(Xh, Xl, WQKVh, WQKVl, nullptr,
        nullptr, QKVh, QKVl, 1024, 1024, 1024, LDQKV, 1.0f);
    transpose_bf16_k<<<dim3(2, 64, 32), 256>>>(Vh, Vl, Vth, Vtl, LDQKV, SEQ,
        (long long)SEQ * LDQKV, 64, (long long)NHEADS * ZVT, ZVT, NHEADS);
    flash_attn_k<<<dim3(16, 32, 1), 256, SMFA>>>(Qh, Ql, Kh, Kl, Vth, Vtl, mask,
                                                 Cxh, Cxl, LDQKV);
    mma_gemm<256, 1, 0><<<dim3(4, 32, 1), 256, SMG>>>(Cxh, Cxl, WOh, WOl, wo_b,
        AO, nullptr, nullptr, 1024, 1024, 1024, 1024, 1.0f);
    add_ln_k<true><<<MTOK, 256>>>(x, AO, g1, be1, X1, X1h, X1l);
    mma_gemm<256, 2, 1><<<dim3(16, 32, 1), 256, SMG>>>(X1h, X1l, W1h, W1l, b1,
        nullptr, Hh, Hl, 1024, 1024, 1024, 4096, 1.0f);
    transpose_split_k<<<dim3(32, 128, 1), 256>>>(w2, W2h, W2l, 1024, 4096);
    mma_gemm<256, 1, 0><<<dim3(4, 32, 1), 256, SMG>>>(Hh, Hl, W2h, W2l, b2,
        FF, nullptr, nullptr, 4096, 4096, 4096, 1024, 1.0f);
    add_ln_k<false><<<MTOK, 256>>>(X1, FF, g2, be2, out, nullptr, nullptr);
}